// round 2
// baseline (speedup 1.0000x reference)
#include <cuda_runtime.h>
#include <cstdint>

// BilateralFilter: x [2,3,384,384] fp32, ksize=9 (sigma=1.7), reflect pad.
//
// Exact simplification: both normalizations in the reference cancel in the
// final ratio, so  out = sum_t w_t p_t / sum_t w_t  with
//   w_t = exp(-(d^2 + ry^2 + rx^2)/(2 s^2)) = G(ry) * G(rx) * exp(-A d^2)
//   A = 1/(2 s^2),  G(k) = exp(-A k^2)   (5 distinct ring constants)
// d = p - center in [-1,1] => d^2 in [0,1] => exp(-A v) on [0,1] is
// approximated by a degree-2 Chebyshev poly (max abs err ~2.7e-5, far under
// the 1e-3 tolerance). No MUFU in the inner loop.
//
// Each thread computes 2 horizontally adjacent pixels using packed f32x2
// FMA-pipe ops; tap pairs come from float2 shared loads.

#define RAD   4
#define KS    9
#define H     384
#define W     384
#define NCH   6
#define BXT   32        // threads x
#define BYT   16        // threads y
#define TW    64        // output tile width  (2 px per thread)
#define TH    16        // output tile height
#define SWD   (TW + 2*RAD)   // 72
#define SHT   (TH + 2*RAD)   // 24

typedef unsigned long long u64;

__device__ __forceinline__ u64 PK(float lo, float hi) {
    u64 r; asm("mov.b64 %0, {%1, %2};" : "=l"(r) : "f"(lo), "f"(hi)); return r;
}
__device__ __forceinline__ void UPK(u64 v, float& lo, float& hi) {
    asm("mov.b64 {%0, %1}, %2;" : "=f"(lo), "=f"(hi) : "l"(v));
}
__device__ __forceinline__ u64 FMA2(u64 a, u64 b, u64 c) {
    u64 d; asm("fma.rn.f32x2 %0, %1, %2, %3;" : "=l"(d) : "l"(a), "l"(b), "l"(c)); return d;
}
__device__ __forceinline__ u64 MUL2(u64 a, u64 b) {
    u64 d; asm("mul.rn.f32x2 %0, %1, %2;" : "=l"(d) : "l"(a), "l"(b)); return d;
}
__device__ __forceinline__ u64 ADD2(u64 a, u64 b) {
    u64 d; asm("add.rn.f32x2 %0, %1, %2;" : "=l"(d) : "l"(a), "l"(b)); return d;
}

__device__ __forceinline__ int reflect_idx(int i, int n) {
    if (i < 0)  i = -i;
    if (i >= n) i = 2 * n - 2 - i;
    return i;
}

// degree-2 Chebyshev approx of exp(-A*v), v in [0,1], A = 1/(2*1.7^2)
#define PC0  0.99997549f
#define PC1 -0.17255621f
#define PC2  0.01373464f
#define AEXP 0.173010380622837f

__global__ __launch_bounds__(BXT * BYT, 2)
void bilateral_kernel(const float* __restrict__ x, float* __restrict__ out) {
    __shared__ float s[SHT][SWD];

    const int ch = blockIdx.z;
    const int bx = blockIdx.x * TW;
    const int by = blockIdx.y * TH;
    const float* __restrict__ xin = x + (size_t)ch * H * W;

    const int tx = threadIdx.x;
    const int ty = threadIdx.y;
    const int tid = ty * BXT + tx;

    // cooperative load 72x24 halo tile (1728 elems / 512 threads)
    #pragma unroll
    for (int i = tid; i < SHT * SWD; i += BXT * BYT) {
        const int ly = i / SWD;
        const int lx = i - ly * SWD;
        const int gy = reflect_idx(by + ly - RAD, H);
        const int gx = reflect_idx(bx + lx - RAD, W);
        s[ly][lx] = xin[gy * W + gx];
    }
    __syncthreads();

    // ring constants G(k) = exp(-A k^2), replicated into packed regs
    u64 G2[5];
    #pragma unroll
    for (int k = 0; k < 5; k++) {
        const float g = expf(-AEXP * (float)(k * k));
        G2[k] = PK(g, g);
    }
    const u64 C0p = PK(PC0, PC0);
    const u64 C1p = PK(PC1, PC1);
    const u64 C2p = PK(PC2, PC2);

    const int c0 = 2 * tx;   // smem col of a[0] (= global bx + 2tx - 4)

    const float2 ctr = *(const float2*)&s[ty + RAD][c0 + RAD];
    const u64 nctr = PK(-ctr.x, -ctr.y);

    u64 sw  = PK(0.0f, 0.0f);
    u64 swp = PK(0.0f, 0.0f);

    #pragma unroll
    for (int dy = 0; dy < KS; dy++) {
        const float* __restrict__ row = &s[ty + dy][c0];
        float a[10];
        #pragma unroll
        for (int j = 0; j < 5; j++) {
            const float2 t = *(const float2*)&row[2 * j];
            a[2 * j]     = t.x;
            a[2 * j + 1] = t.y;
        }
        u64 rs  = PK(0.0f, 0.0f);
        u64 rsp = PK(0.0f, 0.0f);
        #pragma unroll
        for (int o = 0; o < KS; o++) {
            const int k = (o < 4) ? (4 - o) : (o - 4);
            const u64 p = PK(a[o], a[o + 1]);
            const u64 d = ADD2(p, nctr);
            const u64 v = MUL2(d, d);
            u64 q = FMA2(v, C2p, C1p);
            q = FMA2(v, q, C0p);
            const u64 e = MUL2(q, G2[k]);
            rs  = ADD2(rs, e);
            rsp = FMA2(e, p, rsp);
        }
        const int kr = (dy < 4) ? (4 - dy) : (dy - 4);
        sw  = FMA2(rs,  G2[kr], sw);
        swp = FMA2(rsp, G2[kr], swp);
    }

    float swl, swh, spl, sph;
    UPK(sw, swl, swh);
    UPK(swp, spl, sph);
    float2 o2;
    o2.x = __fdividef(spl, swl);
    o2.y = __fdividef(sph, swh);
    *(float2*)&out[(size_t)ch * H * W + (by + ty) * W + bx + c0] = o2;
}

extern "C" void kernel_launch(void* const* d_in, const int* in_sizes, int n_in,
                              void* d_out, int out_size) {
    const float* x = (const float*)d_in[0];
    float* out = (float*)d_out;
    (void)in_sizes; (void)n_in; (void)out_size;

    dim3 block(BXT, BYT, 1);
    dim3 grid(W / TW, H / TH, NCH);   // 6 x 24 x 6
    bilateral_kernel<<<grid, block>>>(x, out);
}

// round 3
// speedup vs baseline: 1.0572x; 1.0572x over previous
#include <cuda_runtime.h>
#include <cstdint>

// BilateralFilter: x [2,3,384,384] fp32, ksize=9 (sigma=1.7), reflect pad.
//
// out = sum_t w_t p_t / sum_t w_t,  w_t = G(ry) G(rx) exp(-A d^2), A=1/(2*1.7^2)
// (both reference normalizations cancel in the ratio). exp(-A v), v=d^2 in
// [0,1], approximated by degree-2 Chebyshev poly (max err ~2.7e-5 << 1e-3).
//
// Each thread computes a VERTICAL pixel pair (Y, Y+1). Shared memory holds
// pre-packed vertical pairs sp[r][c] = (x[r][c], x[r+1][c]), so every tap is
// a single aligned LDS.64 already in f32x2 form: zero packing MOVs.
// Inner loop per pair-tap: 1 LDS.64 + 7 packed f32x2 FMA-pipe ops.

#define RAD   4
#define KS    9
#define H     384
#define W     384
#define NCH   6
#define BXT   32
#define BYT   16
#define TW    32            // output tile width
#define TH    32            // output tile height (2 rows per thread)
#define SROWS (TH + 2*RAD)  // 40 pair-rows
#define SCOLS (TW + 2*RAD)  // 40 cols

typedef unsigned long long u64;

__device__ __forceinline__ u64 PK(float lo, float hi) {
    u64 r; asm("mov.b64 %0, {%1, %2};" : "=l"(r) : "f"(lo), "f"(hi)); return r;
}
__device__ __forceinline__ void UPK(u64 v, float& lo, float& hi) {
    asm("mov.b64 {%0, %1}, %2;" : "=f"(lo), "=f"(hi) : "l"(v));
}
__device__ __forceinline__ u64 FMA2(u64 a, u64 b, u64 c) {
    u64 d; asm("fma.rn.f32x2 %0, %1, %2, %3;" : "=l"(d) : "l"(a), "l"(b), "l"(c)); return d;
}
__device__ __forceinline__ u64 MUL2(u64 a, u64 b) {
    u64 d; asm("mul.rn.f32x2 %0, %1, %2;" : "=l"(d) : "l"(a), "l"(b)); return d;
}
__device__ __forceinline__ u64 ADD2(u64 a, u64 b) {
    u64 d; asm("add.rn.f32x2 %0, %1, %2;" : "=l"(d) : "l"(a), "l"(b)); return d;
}

__device__ __forceinline__ int reflect_idx(int i, int n) {
    if (i < 0)  i = -i;
    if (i >= n) i = 2 * n - 2 - i;
    return i;
}

// degree-2 Chebyshev approx of exp(-A*v), v in [0,1], A = 1/(2*1.7^2)
#define PC0  0.99997549f
#define PC1 -0.17255621f
#define PC2  0.01373464f
// G(k) = exp(-A k^2)
#define G0 1.0f
#define G1 0.84113294f
#define G2v 0.50055903f
#define G3 0.21074724f
#define G4 0.06278940f

__global__ __launch_bounds__(BXT * BYT, 2)
void bilateral_kernel(const float* __restrict__ x, float* __restrict__ out) {
    __shared__ float2 sp[SROWS][SCOLS];

    const int ch = blockIdx.z;
    const int bx = blockIdx.x * TW;
    const int by = blockIdx.y * TH;
    const float* __restrict__ xin = x + (size_t)ch * H * W;

    const int tx = threadIdx.x;
    const int ty = threadIdx.y;
    const int tid = ty * BXT + tx;

    // Build packed vertical-pair tile: sp[r][c] = (x[by+r-4][..], x[by+r-3][..])
    #pragma unroll
    for (int i = tid; i < SROWS * SCOLS; i += BXT * BYT) {
        const int r = i / SCOLS;
        const int c = i - r * SCOLS;
        const int gx  = reflect_idx(bx + c - RAD, W);
        const int gy0 = reflect_idx(by + r - RAD, H);
        const int gy1 = reflect_idx(by + r - RAD + 1, H);
        sp[r][c] = make_float2(xin[gy0 * W + gx], xin[gy1 * W + gx]);
    }
    __syncthreads();

    const float gring[5] = {G0, G1, G2v, G3, G4};
    u64 Gp[5];
    #pragma unroll
    for (int k = 0; k < 5; k++) Gp[k] = PK(gring[k], gring[k]);
    const u64 C0p = PK(PC0, PC0);
    const u64 C1p = PK(PC1, PC1);
    const u64 C2p = PK(PC2, PC2);

    const int Yl = 2 * ty;            // local row of first pixel of the pair

    const float2 ctr = sp[Yl + RAD][tx + RAD];
    const u64 nctr = PK(-ctr.x, -ctr.y);

    u64 sw  = PK(0.0f, 0.0f);
    u64 swp = PK(0.0f, 0.0f);

    #pragma unroll
    for (int dy = 0; dy < KS; dy++) {
        const u64* __restrict__ row = (const u64*)&sp[Yl + dy][tx];
        u64 rs  = PK(0.0f, 0.0f);
        u64 rsp = PK(0.0f, 0.0f);
        #pragma unroll
        for (int dx = 0; dx < KS; dx++) {
            const int k = (dx < RAD) ? (RAD - dx) : (dx - RAD);
            const u64 p = row[dx];              // LDS.64, already packed pair
            const u64 d = ADD2(p, nctr);
            const u64 v = MUL2(d, d);
            u64 q = FMA2(v, C2p, C1p);
            q = FMA2(v, q, C0p);
            const u64 e = MUL2(q, Gp[k]);
            rs  = ADD2(rs, e);
            rsp = FMA2(e, p, rsp);
        }
        const int kr = (dy < RAD) ? (RAD - dy) : (dy - RAD);
        sw  = FMA2(rs,  Gp[kr], sw);
        swp = FMA2(rsp, Gp[kr], swp);
    }

    float swl, swh, spl, sph;
    UPK(sw, swl, swh);
    UPK(swp, spl, sph);

    float* __restrict__ o = out + (size_t)ch * H * W + (by + Yl) * W + bx + tx;
    o[0] = __fdividef(spl, swl);
    o[W] = __fdividef(sph, swh);
}

extern "C" void kernel_launch(void* const* d_in, const int* in_sizes, int n_in,
                              void* d_out, int out_size) {
    const float* x = (const float*)d_in[0];
    float* out = (float*)d_out;
    (void)in_sizes; (void)n_in; (void)out_size;

    dim3 block(BXT, BYT, 1);
    dim3 grid(W / TW, H / TH, NCH);   // 12 x 12 x 6
    bilateral_kernel<<<grid, block>>>(x, out);
}

// round 4
// speedup vs baseline: 1.2980x; 1.2278x over previous
#include <cuda_runtime.h>
#include <cstdint>

// BilateralFilter: x [2,3,384,384] fp32, ksize=9 (sigma=1.7), reflect pad.
//
// out = sum_t w_t p_t / sum_t w_t,  w_t = G(ry)G(rx) exp(-A d^2), A=1/(2*1.7^2)
// (both reference normalizations cancel in the ratio).
//
// exp(-A v), v=d^2 in [0,1], replaced by its degree-1 minimax polynomial
// P(v) = 0.9982830 - 0.1588712 v  (max abs err 1.72e-3 on a weight; after the
// 81-tap weighted-mean cancellation ~1e-4 on the output, tolerance 1e-3).
// The column ring factor G(rx) is folded into the coefficients, and the
// quadratic is expanded around the per-thread center c:
//   e = B1k (p-c)^2 + B0k = fma(p, fma(p, B1k, -2 B1k c), B1k c^2 + B0k)
// => 4 packed f32x2 FMA-pipe ops per vertical-pixel-pair tap, 1 LDS.64.
//
// Shared memory holds pre-packed vertical pairs sp[r][c] = (x[r], x[r+1]).

#define RAD   4
#define KS    9
#define H     384
#define W     384
#define NCH   6
#define BXT   32
#define BYT   8
#define TW    32            // output tile width
#define TH    16            // output tile height (2 rows per thread)
#define SROWS (TH + 2*RAD)  // 24 pair-rows
#define SCOLS (TW + 2*RAD)  // 40 cols

typedef unsigned long long u64;

__device__ __forceinline__ u64 PK(float lo, float hi) {
    u64 r; asm("mov.b64 %0, {%1, %2};" : "=l"(r) : "f"(lo), "f"(hi)); return r;
}
__device__ __forceinline__ void UPK(u64 v, float& lo, float& hi) {
    asm("mov.b64 {%0, %1}, %2;" : "=f"(lo), "=f"(hi) : "l"(v));
}
__device__ __forceinline__ u64 FMA2(u64 a, u64 b, u64 c) {
    u64 d; asm("fma.rn.f32x2 %0, %1, %2, %3;" : "=l"(d) : "l"(a), "l"(b), "l"(c)); return d;
}
__device__ __forceinline__ u64 MUL2(u64 a, u64 b) {
    u64 d; asm("mul.rn.f32x2 %0, %1, %2;" : "=l"(d) : "l"(a), "l"(b)); return d;
}
__device__ __forceinline__ u64 ADD2(u64 a, u64 b) {
    u64 d; asm("add.rn.f32x2 %0, %1, %2;" : "=l"(d) : "l"(a), "l"(b)); return d;
}

__device__ __forceinline__ int reflect_idx(int i, int n) {
    if (i < 0)  i = -i;
    if (i >= n) i = 2 * n - 2 - i;
    return i;
}

// minimax deg-1 of exp(-A v) on [0,1]:  P0 + P1 v
#define P0f  0.9982830f
#define P1f (-0.1588712f)
// ring Gaussians G(k) = exp(-A k^2)
#define Gk0 1.0f
#define Gk1 0.84112877f
#define Gk2 0.50055314f
#define Gk3 0.21074760f
#define Gk4 0.06277703f

__global__ __launch_bounds__(BXT * BYT, 4)
void bilateral_kernel(const float* __restrict__ x, float* __restrict__ out) {
    __shared__ float2 sp[SROWS][SCOLS];

    const int ch = blockIdx.z;
    const int bx = blockIdx.x * TW;
    const int by = blockIdx.y * TH;
    const float* __restrict__ xin = x + (size_t)ch * H * W;

    const int tx = threadIdx.x;
    const int ty = threadIdx.y;
    const int tid = ty * BXT + tx;

    // Build packed vertical-pair tile: sp[r][c] = (x[by+r-4][..], x[by+r-3][..])
    #pragma unroll
    for (int i = tid; i < SROWS * SCOLS; i += BXT * BYT) {
        const int r = i / SCOLS;
        const int c = i - r * SCOLS;
        const int gx  = reflect_idx(bx + c - RAD, W);
        const int gy0 = reflect_idx(by + r - RAD, H);
        const int gy1 = reflect_idx(by + r - RAD + 1, H);
        sp[r][c] = make_float2(xin[gy0 * W + gx], xin[gy1 * W + gx]);
    }
    __syncthreads();

    const float gring[5] = {Gk0, Gk1, Gk2, Gk3, Gk4};

    const int Yl = 2 * ty;            // local row of first pixel of pair
    const float2 ctr = sp[Yl + RAD][tx + RAD];
    const u64 cpk = PK(ctr.x, ctr.y);

    // Per-thread folded constants per column ring k:
    //   B1k = Gk * P1,  nu_k = -2 B1k c,  w_k = B1k c^2 + B0k  (B0k = Gk*P0)
    u64 B1p[5], NUp[5], Wp[5], Grow[5];
    #pragma unroll
    for (int k = 0; k < 5; k++) {
        const float b1 = gring[k] * P1f;
        const float b0 = gring[k] * P0f;
        const u64 b1p  = PK(b1, b1);
        const u64 n2b1 = PK(-2.0f * b1, -2.0f * b1);
        B1p[k] = b1p;
        NUp[k] = MUL2(n2b1, cpk);                  // -2 B1k c
        Wp[k]  = FMA2(MUL2(b1p, cpk), cpk, PK(b0, b0));  // B1k c^2 + B0k
        Grow[k] = PK(gring[k], gring[k]);
    }

    u64 sw  = PK(0.0f, 0.0f);
    u64 swp = PK(0.0f, 0.0f);

    #pragma unroll
    for (int dy = 0; dy < KS; dy++) {
        const u64* __restrict__ row = (const u64*)&sp[Yl + dy][tx];
        // two accumulation chains for ILP
        u64 rs0  = PK(0.0f, 0.0f), rs1  = PK(0.0f, 0.0f);
        u64 rsp0 = PK(0.0f, 0.0f), rsp1 = PK(0.0f, 0.0f);
        #pragma unroll
        for (int dx = 0; dx < KS; dx++) {
            const int k = (dx < RAD) ? (RAD - dx) : (dx - RAD);
            const u64 p = row[dx];                  // LDS.64, packed pair
            const u64 q = FMA2(p, B1p[k], NUp[k]);
            const u64 e = FMA2(p, q, Wp[k]);
            if (dx & 1) { rs1 = ADD2(rs1, e); rsp1 = FMA2(e, p, rsp1); }
            else        { rs0 = ADD2(rs0, e); rsp0 = FMA2(e, p, rsp0); }
        }
        const int kr = (dy < RAD) ? (RAD - dy) : (dy - RAD);
        const u64 rs  = ADD2(rs0, rs1);
        const u64 rsp = ADD2(rsp0, rsp1);
        sw  = FMA2(rs,  Grow[kr], sw);
        swp = FMA2(rsp, Grow[kr], swp);
    }

    float swl, swh, spl, sph;
    UPK(sw, swl, swh);
    UPK(swp, spl, sph);

    float* __restrict__ o = out + (size_t)ch * H * W + (by + Yl) * W + bx + tx;
    o[0] = __fdividef(spl, swl);
    o[W] = __fdividef(sph, swh);
}

extern "C" void kernel_launch(void* const* d_in, const int* in_sizes, int n_in,
                              void* d_out, int out_size) {
    const float* x = (const float*)d_in[0];
    float* out = (float*)d_out;
    (void)in_sizes; (void)n_in; (void)out_size;

    dim3 block(BXT, BYT, 1);
    dim3 grid(W / TW, H / TH, NCH);   // 12 x 24 x 6
    bilateral_kernel<<<grid, block>>>(x, out);
}